// round 1
// baseline (speedup 1.0000x reference)
#include <cuda_runtime.h>
#include <math.h>

#define BB 2
#define TT 2048
#define DD 1024
#define HH 16
#define HD 64
#define MROWS (BB*TT)   // 4096

// Scratch buffers (allocation-free rule: __device__ globals)
__device__ float g_q[MROWS*DD];
__device__ float g_k[MROWS*DD];
__device__ float g_v[MROWS*DD];
__device__ float g_att[MROWS*DD];

// ---------------------------------------------------------------------------
// GEMM: C[M,N] = A[M,K] @ W[K,N] + bias[N]   (all row-major, fp32)
// 64x64 tile, BK=16, 256 threads, 4x4 per-thread micro-tile.
// ---------------------------------------------------------------------------
#define GBM 64
#define GBN 64
#define GBK 16

__global__ __launch_bounds__(256) void gemm_bias_kernel(
    const float* __restrict__ A, const float* __restrict__ W,
    const float* __restrict__ bias, float* __restrict__ C,
    int M, int N, int K)
{
    __shared__ float As[GBK][GBM];   // A tile stored transposed: As[k][m]
    __shared__ float Ws[GBK][GBN];

    const int tid = threadIdx.x;
    const int m0 = blockIdx.y * GBM;
    const int n0 = blockIdx.x * GBN;
    const int tx = tid & 15;         // 0..15 -> N
    const int ty = tid >> 4;         // 0..15 -> M

    // load indices
    const int arow  = tid >> 2;          // 0..63
    const int acol4 = (tid & 3) << 2;    // 0,4,8,12
    const int wrow  = tid >> 4;          // 0..15
    const int wcol4 = (tid & 15) << 2;   // 0..60

    float acc[4][4];
    #pragma unroll
    for (int i = 0; i < 4; i++)
        #pragma unroll
        for (int j = 0; j < 4; j++) acc[i][j] = 0.f;

    for (int k0 = 0; k0 < K; k0 += GBK) {
        float4 av = *(const float4*)(A + (size_t)(m0 + arow) * K + k0 + acol4);
        As[acol4 + 0][arow] = av.x;
        As[acol4 + 1][arow] = av.y;
        As[acol4 + 2][arow] = av.z;
        As[acol4 + 3][arow] = av.w;
        *(float4*)(&Ws[wrow][wcol4]) =
            *(const float4*)(W + (size_t)(k0 + wrow) * N + n0 + wcol4);
        __syncthreads();

        #pragma unroll
        for (int k = 0; k < GBK; k++) {
            float a[4], w[4];
            *(float4*)a = *(const float4*)(&As[k][ty << 2]);
            *(float4*)w = *(const float4*)(&Ws[k][tx << 2]);
            #pragma unroll
            for (int i = 0; i < 4; i++)
                #pragma unroll
                for (int j = 0; j < 4; j++)
                    acc[i][j] += a[i] * w[j];
        }
        __syncthreads();
    }

    #pragma unroll
    for (int i = 0; i < 4; i++) {
        const int row = m0 + (ty << 2) + i;
        float4 outv;
        const int col = n0 + (tx << 2);
        outv.x = acc[i][0] + bias[col + 0];
        outv.y = acc[i][1] + bias[col + 1];
        outv.z = acc[i][2] + bias[col + 2];
        outv.w = acc[i][3] + bias[col + 3];
        *(float4*)(C + (size_t)row * N + col) = outv;
    }
}

// ---------------------------------------------------------------------------
// Flash-style causal attention (fp32, hd=64).
// Block: 128 threads, 128 query rows (one per thread) for one (b,h).
// Loop over 64-key tiles, K/V staged in SMEM, scores in padded SMEM,
// online softmax; accumulator o[64] in registers.
// ---------------------------------------------------------------------------
#define AM 128
#define AN 64
#define ATTN_SMEM ((2*AN*HD + AM*(AN+1)) * 4)  // 66048 bytes

__global__ __launch_bounds__(128, 2) void attn_kernel(
    const float* __restrict__ Q, const float* __restrict__ Kg,
    const float* __restrict__ Vg, float* __restrict__ O)
{
    extern __shared__ float sm[];
    float* Ks = sm;                 // [AN][HD]
    float* Vs = sm + AN * HD;       // [AN][HD]
    float* Ss = sm + 2 * AN * HD;   // [AM][AN+1]  (pad to kill bank conflicts)

    const int tid = threadIdx.x;
    const int q0  = blockIdx.x * AM;
    const int b   = blockIdx.y >> 4;
    const int h   = blockIdx.y & 15;
    const int q_idx = q0 + tid;

    // Load this thread's query row into registers
    const float* qp = Q + ((size_t)(b * TT + q_idx)) * DD + h * HD;
    float q[HD];
    #pragma unroll
    for (int d = 0; d < HD; d += 4) {
        float4 t4 = *(const float4*)(qp + d);
        q[d] = t4.x; q[d+1] = t4.y; q[d+2] = t4.z; q[d+3] = t4.w;
    }

    float o[HD];
    #pragma unroll
    for (int d = 0; d < HD; d++) o[d] = 0.f;
    float mval = -1e30f, l = 0.f;

    float* srow = Ss + tid * (AN + 1);
    const int nt = q0 / AN + 2;   // key tiles needed (causal)

    for (int kt = 0; kt < nt; kt++) {
        __syncthreads();   // protect previous tile reads
        const int sbase = kt * AN;
        const float* kg = Kg + ((size_t)(b * TT + sbase)) * DD + h * HD;
        const float* vg = Vg + ((size_t)(b * TT + sbase)) * DD + h * HD;

        // cooperative K/V tile load (1024 float4 each)
        for (int i = tid; i < AN * HD / 4; i += AM) {
            const int r = i >> 4;
            const int c = (i & 15) << 2;
            *(float4*)(Ks + r * HD + c) = *(const float4*)(kg + (size_t)r * DD + c);
            *(float4*)(Vs + r * HD + c) = *(const float4*)(vg + (size_t)r * DD + c);
        }
        __syncthreads();

        // scores for this thread's query row
        float tmax = -1e30f;
        for (int j = 0; j < AN; j++) {
            const float* kr = Ks + j * HD;
            float s = 0.f;
            #pragma unroll
            for (int d = 0; d < HD; d += 4) {
                float4 k4 = *(const float4*)(kr + d);
                s += q[d]   * k4.x;
                s += q[d+1] * k4.y;
                s += q[d+2] * k4.z;
                s += q[d+3] * k4.w;
            }
            s *= 0.125f;                      // hd^-0.5
            if (sbase + j > q_idx) s = -1e30f; // causal mask
            srow[j] = s;
            tmax = fmaxf(tmax, s);
        }

        // online softmax rescale
        const float mnew  = fmaxf(mval, tmax);
        const float alpha = __expf(mval - mnew);
        l *= alpha;
        #pragma unroll
        for (int d = 0; d < HD; d++) o[d] *= alpha;

        for (int j = 0; j < AN; j++) {
            const float p = __expf(srow[j] - mnew);
            l += p;
            const float* vr = Vs + j * HD;
            #pragma unroll
            for (int d = 0; d < HD; d += 4) {
                float4 v4 = *(const float4*)(vr + d);
                o[d]   += p * v4.x;
                o[d+1] += p * v4.y;
                o[d+2] += p * v4.z;
                o[d+3] += p * v4.w;
            }
        }
        mval = mnew;
    }

    const float inv = 1.f / l;
    float* op = O + ((size_t)(b * TT + q_idx)) * DD + h * HD;
    #pragma unroll
    for (int d = 0; d < HD; d += 4) {
        float4 r4 = make_float4(o[d] * inv, o[d+1] * inv, o[d+2] * inv, o[d+3] * inv);
        *(float4*)(op + d) = r4;
    }
}

// ---------------------------------------------------------------------------
extern "C" void kernel_launch(void* const* d_in, const int* in_sizes, int n_in,
                              void* d_out, int out_size)
{
    (void)in_sizes; (void)n_in; (void)out_size;
    const float* x  = (const float*)d_in[0];
    // d_in[1] = mask (pure causal, applied analytically in-kernel)
    const float* Wq = (const float*)d_in[2];
    const float* bq = (const float*)d_in[3];
    const float* Wk = (const float*)d_in[4];
    const float* bk = (const float*)d_in[5];
    const float* Wv = (const float*)d_in[6];
    const float* bv = (const float*)d_in[7];
    const float* Wo = (const float*)d_in[8];
    const float* bo = (const float*)d_in[9];
    float* out = (float*)d_out;

    float *q, *k, *v, *att;
    cudaGetSymbolAddress((void**)&q,   g_q);
    cudaGetSymbolAddress((void**)&k,   g_k);
    cudaGetSymbolAddress((void**)&v,   g_v);
    cudaGetSymbolAddress((void**)&att, g_att);

    cudaFuncSetAttribute(attn_kernel,
                         cudaFuncAttributeMaxDynamicSharedMemorySize, ATTN_SMEM);

    dim3 gg(DD / GBN, MROWS / GBM);   // (16, 64)
    gemm_bias_kernel<<<gg, 256>>>(x, Wq, bq, q, MROWS, DD, DD);
    gemm_bias_kernel<<<gg, 256>>>(x, Wk, bk, k, MROWS, DD, DD);
    gemm_bias_kernel<<<gg, 256>>>(x, Wv, bv, v, MROWS, DD, DD);

    attn_kernel<<<dim3(TT / AM, BB * HH), AM, ATTN_SMEM>>>(q, k, v, att);

    gemm_bias_kernel<<<gg, 256>>>(att, Wo, bo, out, MROWS, DD, DD);
}